// round 7
// baseline (speedup 1.0000x reference)
#include <cuda_runtime.h>
#include <cstdint>

#define N 2048
#define D 128
#define E 16384
#define OUTCOLS (2 * E)
#define THREADS 256
#define CHUNK4 512                       // float4 per warp-claimed zero chunk (8 KB)
#define NCHUNK ((N * (size_t)OUTCOLS / 4) / CHUNK4)   // 32768 chunks

// ---------------------------------------------------------------------------
// Persistent-kernel shared state (device globals — no allocation allowed).
// All counters re-zeroed by k_init every launch (graph replays reuse them).
// ---------------------------------------------------------------------------
__device__ int            g_is64;
__device__ float          g_ej[N];
__device__ float          g_Z[N];
__device__ int            g_src_i[E];
__device__ int            g_dst_i[E];
__device__ unsigned       g_row_ctr;
__device__ unsigned       g_zero_ctr;
__device__ unsigned       g_pre_done;
__device__ unsigned       g_bar;
__device__ volatile int   g_flag_ej;

// ---------------------------------------------------------------------------
// Init: reset counters + detect edge dtype (i64 values are all < N when read
// as u64; i32 data reinterpreted packs two indices per word -> >= N).
// ---------------------------------------------------------------------------
__global__ void k_init(const unsigned long long* __restrict__ e64) {
    if (threadIdx.x == 0) {
        g_row_ctr = 0; g_zero_ctr = 0; g_pre_done = 0; g_bar = 0; g_flag_ej = 0;
        int ok = 1;
        for (int i = 0; i < 64; i++)
            if (e64[i] >= (unsigned long long)N) { ok = 0; break; }
        g_is64 = ok;
    }
}

// ---------------------------------------------------------------------------
// Fused persistent kernel. grid = 2 * SM count (all blocks co-resident).
//
// Prelude (block-specialized):
//   blocks 0..7  : edge index convert (i64/i32 -> int32, clamped)
//   blocks 8..23 : u = W1^T @ W2[0,D:], then ej[row] = exp(X[row,:].u)
//                  (no max subtraction: sj ~ N(0,2); softmax ratios identical)
//                  last finisher sets g_flag_ej.
// Main loop (warp-granular work stealing):
//   priority 1: once flag_ej, claim Z rows (16 MB adj read, MLP-16 __ldcs)
//   priority 2: claim 8 KB zero-store chunks of the 256 MB output (__stcs)
//   -> adj reads overlap the store stream instead of serializing before it.
// Grid barrier (all resident), then scatter: compute ap/ac per edge in place
// and write the 2*E nonzero outputs.
// ---------------------------------------------------------------------------
__global__ void __launch_bounds__(THREADS, 2)
k_fused(const float* __restrict__ X,
        const void*  __restrict__ edges,
        const int*   __restrict__ adj,
        const float* __restrict__ W1,
        const float* __restrict__ W2,
        float4*      __restrict__ out4) {
    const int bid  = blockIdx.x;
    const int t    = threadIdx.x;
    const int lane = t & 31;
    const int warp = t >> 5;
    const unsigned FULL = 0xffffffffu;

    __shared__ float us[D];

    // ---------------- prelude ----------------
    if (bid < 8) {
        // edge convert: 4096 indices per block
        int base = bid * 4096;
        if (g_is64) {
            const long long* e = (const long long*)edges;
            for (int i = t; i < 4096; i += THREADS) {
                int idx = base + i;
                int v = (int)e[idx];
                if ((unsigned)v >= (unsigned)N) v = 0;
                if (idx < E) g_src_i[idx] = v; else g_dst_i[idx - E] = v;
            }
        } else {
            const int* e = (const int*)edges;
            for (int i = t; i < 4096; i += THREADS) {
                int idx = base + i;
                int v = e[idx];
                if ((unsigned)v >= (unsigned)N) v = 0;
                if (idx < E) g_src_i[idx] = v; else g_dst_i[idx - E] = v;
            }
        }
    } else if (bid < 24) {
        // u[c] = sum_d W1[d,c] * W2[D+d]   (redundant per block, 16K FMA)
        if (t < D) {
            float acc = 0.f;
#pragma unroll 8
            for (int d = 0; d < D; d++) acc += W1[d * D + t] * W2[D + d];
            us[t] = acc;
        }
        __syncthreads();
        // 128 rows per block, 16 rows per warp; ej[row] = exp(X[row,:].u)
        const float4* X4  = (const float4*)X;
        const float4* us4 = (const float4*)us;
        float4 u4 = us4[lane];
        int row0 = (bid - 8) * 128 + warp * 16;
#pragma unroll
        for (int rr = 0; rr < 16; rr++) {
            int row = row0 + rr;
            float4 x4 = X4[row * 32 + lane];
            float acc = x4.x * u4.x + x4.y * u4.y + x4.z * u4.z + x4.w * u4.w;
#pragma unroll
            for (int o = 16; o; o >>= 1) acc += __shfl_down_sync(FULL, acc, o);
            if (lane == 0) g_ej[row] = expf(acc);
        }
        __syncthreads();
        if (t == 0) {
            __threadfence();
            if (atomicAdd(&g_pre_done, 1u) == 15u) g_flag_ej = 1;
        }
    }

    // ---------------- main work-stealing loop (warp-autonomous) ----------------
    bool z_claimed_all = false;
    const float4* ej4 = (const float4*)g_ej;

    for (;;) {
        if (!z_claimed_all && g_flag_ej) {
            __threadfence();  // acquire: ej writes visible
            for (;;) {
                unsigned r;
                if (lane == 0) r = atomicAdd(&g_row_ctr, 1u);
                r = __shfl_sync(FULL, r, 0);
                if (r >= N) break;
                const int4* ar = (const int4*)(adj + (size_t)r * N);
                float acc = 0.f;
#pragma unroll 8
                for (int i = 0; i < 16; i++) {
                    int k = lane + 32 * i;
                    int4   v = __ldcs(&ar[k]);
                    float4 e = __ldg(&ej4[k]);
                    if (v.x > 0) acc += e.x;
                    if (v.y > 0) acc += e.y;
                    if (v.z > 0) acc += e.z;
                    if (v.w > 0) acc += e.w;
                }
#pragma unroll
                for (int o = 16; o; o >>= 1) acc += __shfl_down_sync(FULL, acc, o);
                if (lane == 0) g_Z[r] = acc;
            }
            __threadfence();  // release Z before this block's barrier arrive
            z_claimed_all = true;
        }

        unsigned z;
        if (lane == 0) z = atomicAdd(&g_zero_ctr, 1u);
        z = __shfl_sync(FULL, z, 0);
        if (z < (unsigned)NCHUNK) {
            float4* p = out4 + (size_t)z * CHUNK4 + lane;
            const float4 zero = make_float4(0.f, 0.f, 0.f, 0.f);
#pragma unroll
            for (int k = 0; k < CHUNK4 / 32; k++) __stcs(p + 32 * k, zero);
            continue;
        }
        if (z_claimed_all) break;
        __nanosleep(64);   // zeros exhausted but ej flag not yet up (rare)
    }

    // ---------------- grid barrier (all blocks resident by construction) -----
    __syncthreads();
    if (t == 0) { __threadfence(); atomicAdd(&g_bar, 1u); }
    while (*((volatile unsigned*)&g_bar) < gridDim.x) { }
    __threadfence();

    // ---------------- scatter the 2*E nonzero outputs ----------------
    float* out = (float*)out4;
    int nt = gridDim.x * THREADS;
    for (int c = bid * THREADS + t; c < E; c += nt) {
        int src = g_src_i[c];
        int dst = g_dst_i[c];
        float ap = (__ldg(&adj[(size_t)dst * N + src]) > 0) ? g_ej[src] / g_Z[dst] : 0.f;
        float ac = (__ldg(&adj[(size_t)src * N + dst]) > 0) ? g_ej[dst] / g_Z[src] : 0.f;
        out[(size_t)dst * OUTCOLS + c]     = ap;
        out[(size_t)src * OUTCOLS + c + E] = ac;
    }
}

// ---------------------------------------------------------------------------
// kernel_launch
// Inputs: X_n [N,D] f32, edge_indices [2,E] i64/i32, adj [N,N] i32,
//         W1 [D,D] f32, W2 [1,2D] f32.  Output: [N, 2E] f32.
// ---------------------------------------------------------------------------
extern "C" void kernel_launch(void* const* d_in, const int* in_sizes, int n_in,
                              void* d_out, int out_size) {
    const float* X     = (const float*)d_in[0];
    const void*  edges = d_in[1];
    const int*   adj   = (const int*)d_in[2];
    const float* W1    = (const float*)d_in[3];
    const float* W2    = (const float*)d_in[4];
    float*       out   = (float*)d_out;

    static int nblk = 0;
    if (nblk == 0) {
        int sm = 0;
        cudaDeviceGetAttribute(&sm, cudaDevAttrMultiProcessorCount, 0);
        if (sm <= 0) sm = 148;
        nblk = 2 * sm;   // exactly 2 blocks/SM -> all co-resident (grid barrier safe)
    }

    k_init<<<1, 32>>>((const unsigned long long*)edges);
    k_fused<<<nblk, THREADS>>>(X, edges, adj, W1, W2, (float4*)out);
}